// round 17
// baseline (speedup 1.0000x reference)
#include <cuda_runtime.h>
#include <cuda_bf16.h>
#include <math.h>
#include <cstdint>

#define Bn 8
#define Cn 64
#define HW 65536
#define Sn 2048
#define OUTC 16

#define F_SCALE     20.6096954f                   /* log2(e)/0.07 */
#define F_LN2       0.69314718056f

typedef unsigned long long ull;
__device__ __forceinline__ ull pack2(float lo, float hi) {
    ull r;
    asm("mov.b64 %0, {%1, %2};" : "=l"(r) : "r"(__float_as_uint(lo)), "r"(__float_as_uint(hi)));
    return r;
}
__device__ __forceinline__ void unpack2(ull v, float& lo, float& hi) {
    unsigned a, b;
    asm("mov.b64 {%0, %1}, %2;" : "=r"(a), "=r"(b) : "l"(v));
    lo = __uint_as_float(a); hi = __uint_as_float(b);
}
#define FMA2(d, a, b) asm("fma.rn.f32x2 %0, %1, %2, %3;" : "=l"(d) : "l"(a), "l"(b), "l"(d))
#define ADD2(d, a)    asm("add.rn.f32x2 %0, %1, %2;"     : "=l"(d) : "l"(a), "l"(d))
__device__ __forceinline__ float ex2f(float x) {
    float y; asm("ex2.approx.f32 %0, %1;" : "=f"(y) : "f"(x)); return y;
}
__device__ __forceinline__ float lg2f(float x) {
    float y; asm("lg2.approx.f32 %0, %1;" : "=f"(y) : "f"(x)); return y;
}
#define PACKBF(d, lo, hi) \
    asm("cvt.rn.bf16x2.f32 %0, %1, %2;" : "=r"(d) : "f"(hi), "f"(lo))

// m16n8k16 bf16 MMA, C = 0
__device__ __forceinline__ void mma16816(float& d0, float& d1, float& d2, float& d3,
                                         uint32_t a0, uint32_t a1, uint32_t a2, uint32_t a3,
                                         uint32_t b0, uint32_t b1) {
    asm("mma.sync.aligned.m16n8k16.row.col.f32.bf16.bf16.f32 "
        "{%0,%1,%2,%3}, {%4,%5,%6,%7}, {%8,%9}, {%10,%11,%12,%13};"
        : "=f"(d0), "=f"(d1), "=f"(d2), "=f"(d3)
        : "r"(a0), "r"(a1), "r"(a2), "r"(a3), "r"(b0), "r"(b1),
          "f"(0.0f), "f"(0.0f), "f"(0.0f), "f"(0.0f));
}

// Scratch
__device__ float g_fq[Bn * Sn * OUTC];
__device__ float g_fk[Bn * Sn * OUTC];
__device__ __align__(16) __nv_bfloat16 g_fqh[Bn * Sn * OUTC];   // PRESCALED by F_SCALE
__device__ __align__(16) __nv_bfloat16 g_fkh[Bn * Sn * OUTC];   // unscaled
__device__ float g_sums[Bn * Sn];
__device__ int   g_cnt[Bn * 32];

// ---------------------------------------------------------------------------
// Kernel AB (fused): gather stencil diffs into smem, MLP + L2-norm.
// Also zeroes out / g_sums / g_cnt.  qh output is prescaled by F_SCALE.
// ---------------------------------------------------------------------------
#define XPAD 68
__global__ __launch_bounds__(256) void gmlp_kernel(const float* __restrict__ fq,
                                                   const float* __restrict__ fk,
                                                   const int*   __restrict__ c_ids,
                                                   const float* __restrict__ W0,
                                                   const float* __restrict__ b0,
                                                   const float* __restrict__ W1,
                                                   const float* __restrict__ b1,
                                                   float* __restrict__ out) {
    extern __shared__ float smem[];
    float* sx  = smem;                       // 256*68
    float* sW0 = sx + 256 * XPAD;            // 64*64 (transposed)
    float* sW1 = sW0 + 64 * 64;              // 64*16
    float* sb0 = sW1 + 64 * 16;              // 64
    float* sb1 = sb0 + 64;                   // 16

    if (blockIdx.x == 0 && threadIdx.x == 0) out[0] = 0.0f;
    if (blockIdx.x < 64) g_sums[blockIdx.x * 256 + threadIdx.x] = 0.0f;
    if (blockIdx.x == 64 && threadIdx.x < Bn * 32) g_cnt[threadIdx.x] = 0;

    int mb    = blockIdx.x >> 3;
    int chunk = blockIdx.x & 7;
    int tid   = threadIdx.x;
    int b     = (mb < Bn) ? mb : mb - Bn;

    for (int i = tid; i < 4096; i += 256) {
        int c = i >> 6, t = i & 63;
        sW0[t * 64 + c] = __ldg(&W0[i]);
    }
    for (int i = tid; i < 1024; i += 256) sW1[i] = __ldg(&W1[i]);
    if (tid < 64) sb0[tid] = __ldg(&b0[tid]);
    if (tid < 16) sb1[tid] = __ldg(&b1[tid]);

    {
        int c   = tid & 63;
        int ce0 = tid >> 6;
        const float* featc = ((mb < Bn) ? fq : fk) + ((size_t)b * Cn + c) * HW;
#pragma unroll
        for (int k = 0; k < 8; k++) {
            int ce = ce0 + 4 * k;
            int ic = __ldg(&c_ids[chunk * 32 + ce]);
            const float* p = featc + ic;
            float fc  = __ldg(p);
            float n0  = __ldg(p - 257);
            float n1  = __ldg(p - 256);
            float n2  = __ldg(p - 255);
            float n3  = __ldg(p - 1);
            float n4  = __ldg(p + 1);
            float n5  = __ldg(p + 255);
            float n6  = __ldg(p + 256);
            float n7  = __ldg(p + 257);
            float* sxr = sx + (size_t)(ce * 8) * XPAD + c;
            sxr[0 * XPAD] = fc - n0;
            sxr[1 * XPAD] = fc - n1;
            sxr[2 * XPAD] = fc - n2;
            sxr[3 * XPAD] = fc - n3;
            sxr[4 * XPAD] = fc - n4;
            sxr[5 * XPAD] = fc - n5;
            sxr[6 * XPAD] = fc - n6;
            sxr[7 * XPAD] = fc - n7;
        }
    }
    __syncthreads();

    ull x2[32];
#pragma unroll
    for (int i = 0; i < 16; i++) {
        float4 v = *reinterpret_cast<float4*>(&sx[tid * XPAD + i * 4]);
        x2[2 * i + 0] = pack2(v.x, v.y);
        x2[2 * i + 1] = pack2(v.z, v.w);
    }

    ull o2[8];
#pragma unroll
    for (int i = 0; i < 8; i++) o2[i] = pack2(sb1[2 * i], sb1[2 * i + 1]);

#pragma unroll 4
    for (int t = 0; t < 64; t++) {
        const ull* w2 = reinterpret_cast<const ull*>(&sW0[t * 64]);
        ull a0 = 0, a1 = 0, a2 = 0, a3 = 0;
#pragma unroll
        for (int i = 0; i < 8; i++) {
            FMA2(a0, x2[i +  0], w2[i +  0]);
            FMA2(a1, x2[i +  8], w2[i +  8]);
            FMA2(a2, x2[i + 16], w2[i + 16]);
            FMA2(a3, x2[i + 24], w2[i + 24]);
        }
        ADD2(a0, a1); ADD2(a2, a3); ADD2(a0, a2);
        float lo, hi; unpack2(a0, lo, hi);
        float h = fmaxf(lo + hi + sb0[t], 0.0f);
        ull h2 = pack2(h, h);
        const ull* w1 = reinterpret_cast<const ull*>(&sW1[t * 16]);
#pragma unroll
        for (int i = 0; i < 8; i++) FMA2(o2[i], h2, w1[i]);
    }

    float o[16];
#pragma unroll
    for (int i = 0; i < 8; i++) unpack2(o2[i], o[2 * i], o[2 * i + 1]);

    float sq = 0.f;
#pragma unroll
    for (int i = 0; i < 16; i++) sq = fmaf(o[i], o[i], sq);
    float inv = 1.0f / (sqrtf(sq) + 1e-7f);
#pragma unroll
    for (int i = 0; i < 16; i++) o[i] *= inv;

    size_t row = (size_t)b * Sn + chunk * 256 + tid;
    float* dst = (mb < Bn ? g_fq : g_fk) + row * OUTC;
#pragma unroll
    for (int oo = 0; oo < 4; oo++)
        *reinterpret_cast<float4*>(&dst[oo * 4]) =
            make_float4(o[oo * 4 + 0], o[oo * 4 + 1], o[oo * 4 + 2], o[oo * 4 + 3]);

    // bf16 copy; q side prescaled by F_SCALE (shift-free exp in gram)
    float sc = (mb < Bn) ? F_SCALE : 1.0f;
    uint32_t hb[8];
#pragma unroll
    for (int i = 0; i < 8; i++) PACKBF(hb[i], o[2 * i] * sc, o[2 * i + 1] * sc);
    uint32_t* dsth = reinterpret_cast<uint32_t*>(
        (mb < Bn ? g_fqh : g_fkh) + row * OUTC);
#pragma unroll
    for (int i = 0; i < 2; i++)
        reinterpret_cast<uint4*>(dsth)[i] =
            make_uint4(hb[4 * i + 0], hb[4 * i + 1], hb[4 * i + 2], hb[4 * i + 3]);
}

// ---------------------------------------------------------------------------
// Kernel C v4: HMMA Gram, t-half split + counter-gated fused finalize.
//   grid = 8b x 32rb x 2th = 512 blocks, 512 threads, 32 KB smem
//   -> 3 blocks/SM (launch_bounds reg cap), ~12 warps/SMSP.
//   MMA emits d' = SCALE*(q.k) directly (qh prescaled); sum' = sum 2^d'.
//   loss_row = ln2*(lg2(sum') - SCALE*d_ss).  Partials merge via atomicAdd
//   into g_sums; last (b,rb) block finalizes its 64 rows.
// ---------------------------------------------------------------------------
__global__ __launch_bounds__(512, 3) void gram_kernel(float* __restrict__ out) {
    extern __shared__ uint32_t sk[];      // B0[1024*4] | B1[1024*4]  (32 KB)
    __shared__ float s_wred[2];
    __shared__ int   s_last;

    int tid  = threadIdx.x;
    int w    = tid >> 5;                  // 0..15
    int lane = tid & 31;
    int g    = lane >> 2;
    int t    = lane & 3;
    int blk  = blockIdx.x;
    int b    = blk >> 6;
    int rb   = (blk >> 1) & 31;
    int th   = blk & 1;                   // t-half
    int wr   = w & 3;                     // row sub-block
    int tq   = w >> 2;                    // t-quarter within half

    uint32_t* B0 = sk;
    uint32_t* B1 = sk + 1024 * 4;

    // stage this half: 1024 k rows
    const uint32_t* ksrc = reinterpret_cast<const uint32_t*>(g_fkh) +
                           (size_t)b * Sn * 8 + (size_t)th * 1024 * 8;
    for (int idx = tid; idx < 1024 * 8; idx += 512) {
        int n = idx >> 3, j = idx & 7;
        uint32_t v = __ldg(&ksrc[idx]);
        if (j < 4) B0[n * 4 + j] = v;
        else       B1[n * 4 + (j - 4)] = v;
    }

    int r0 = rb * 64 + wr * 16 + g;
    const uint32_t* qu = reinterpret_cast<const uint32_t*>(g_fqh) +
                         (size_t)b * Sn * 8;
    uint32_t a0 = __ldg(&qu[(size_t)r0 * 8 + t]);
    uint32_t a1 = __ldg(&qu[(size_t)(r0 + 8) * 8 + t]);
    uint32_t a2 = __ldg(&qu[(size_t)r0 * 8 + t + 4]);
    uint32_t a3 = __ldg(&qu[(size_t)(r0 + 8) * 8 + t + 4]);

    __syncthreads();

    float s0 = 0.f, s1 = 0.f;

    // this warp's t-quarter within the half: n-tiles [tq*32, tq*32+32)
    for (int j = tq * 32; j < tq * 32 + 32; j += 2) {
        int nA = (j + 0) * 8 + g;
        int nB = (j + 1) * 8 + g;
        uint32_t bA0 = B0[nA * 4 + t], bA1 = B1[nA * 4 + t];
        uint32_t bB0 = B0[nB * 4 + t], bB1 = B1[nB * 4 + t];

        float dA0, dA1, dA2, dA3, dB0, dB1, dB2, dB3;
        mma16816(dA0, dA1, dA2, dA3, a0, a1, a2, a3, bA0, bA1);
        mma16816(dB0, dB1, dB2, dB3, a0, a1, a2, a3, bB0, bB1);

        s0 += ex2f(dA0); s0 += ex2f(dA1);
        s1 += ex2f(dA2); s1 += ex2f(dA3);
        s0 += ex2f(dB0); s0 += ex2f(dB1);
        s1 += ex2f(dB2); s1 += ex2f(dB3);
    }

    s0 += __shfl_xor_sync(0xFFFFFFFFu, s0, 1);
    s0 += __shfl_xor_sync(0xFFFFFFFFu, s0, 2);
    s1 += __shfl_xor_sync(0xFFFFFFFFu, s1, 1);
    s1 += __shfl_xor_sync(0xFFFFFFFFu, s1, 2);

    if (t == 0) {
        atomicAdd(&g_sums[(size_t)b * Sn + r0], s0);
        atomicAdd(&g_sums[(size_t)b * Sn + r0 + 8], s1);
    }

    __threadfence();
    __syncthreads();
    if (tid == 0) {
        int old = atomicAdd(&g_cnt[b * 32 + rb], 1);
        s_last = (old == 1);
    }
    __syncthreads();
    if (!s_last) return;

    // finalize this (b,rb)'s 64 rows
    float loss = 0.f;
    if (tid < 64) {
        size_t grow = (size_t)b * Sn + rb * 64 + tid;
        float sum = __ldcg(&g_sums[grow]);
        const float4* qr = reinterpret_cast<const float4*>(g_fq + grow * OUTC);
        const float4* kr = reinterpret_cast<const float4*>(g_fk + grow * OUTC);
        float d = 0.f;
#pragma unroll
        for (int jj = 0; jj < 4; jj++) {
            float4 qv = __ldg(&qr[jj]);
            float4 kv = __ldg(&kr[jj]);
            d = fmaf(qv.x, kv.x, d); d = fmaf(qv.y, kv.y, d);
            d = fmaf(qv.z, kv.z, d); d = fmaf(qv.w, kv.w, d);
        }
        loss = F_LN2 * (lg2f(sum) - F_SCALE * d);
#pragma unroll
        for (int o = 16; o > 0; o >>= 1)
            loss += __shfl_xor_sync(0xFFFFFFFFu, loss, o);
        if (lane == 0) s_wred[w] = loss;
    }
    __syncthreads();
    if (tid == 0)
        atomicAdd(out, (s_wred[0] + s_wred[1]) * (1.0f / (float)(Bn * Sn)));
}

// ---------------------------------------------------------------------------
extern "C" void kernel_launch(void* const* d_in, const int* in_sizes, int n_in,
                              void* d_out, int out_size) {
    const float* f_q  = (const float*)d_in[0];
    const float* f_k  = (const float*)d_in[1];
    const float* W0   = (const float*)d_in[2];
    const float* b0   = (const float*)d_in[3];
    const float* W1   = (const float*)d_in[4];
    const float* b1   = (const float*)d_in[5];
    const int*   c_id = (const int*)d_in[6];
    float* out = (float*)d_out;

    int gmlp_smem = (256 * XPAD + 64 * 64 + 64 * 16 + 64 + 16) * (int)sizeof(float);
    cudaFuncSetAttribute(gmlp_kernel,
                         cudaFuncAttributeMaxDynamicSharedMemorySize, gmlp_smem);
    int gram_smem = 1024 * 8 * (int)sizeof(uint32_t);   // 32 KB
    cudaFuncSetAttribute(gram_kernel,
                         cudaFuncAttributeMaxDynamicSharedMemorySize, gram_smem);

    gmlp_kernel<<<16 * 8, 256, gmlp_smem>>>(f_q, f_k, c_id, W0, b0, W1, b1, out);
    gram_kernel<<<Bn * 64, 512, gram_smem>>>(out);
}